// round 14
// baseline (speedup 1.0000x reference)
#include <cuda_runtime.h>
#include <cstdint>

#define COLS 16384
#define KSEL 256
#define NT   512
#define WCAP 512
#define ROWBYTES (COLS * 4)
#define NCH  4
#define CHBYTES (ROWBYTES / NCH)   // 16384
#define CHF4    (CHBYTES / 16)     // 1024 float4 per chunk
#define CHELEM  (CHBYTES / 4)      // 4096 floats per chunk

// dynamic smem layout
#define OFF_SLIST 65536
#define OFF_HIST  (OFF_SLIST + WCAP * 8)   // 69632
#define OFF_S     (OFF_HIST + 1024)        // 70656
#define OFF_MBAR  (OFF_S + 32)             // 70688
#define SMEM_TOTAL (OFF_MBAR + NCH * 8)    // 70720 -> 3 CTAs/SM

typedef unsigned long long u64;

__device__ __forceinline__ unsigned smem_u32(const void* p) {
    unsigned r;
    asm("{ .reg .u64 t; cvta.to.shared.u64 t, %1; cvt.u32.u64 %0, t; }" : "=r"(r) : "l"(p));
    return r;
}
__device__ __forceinline__ void mbar_wait(unsigned mbar, unsigned phase) {
    asm volatile(
        "{\n\t.reg .pred P;\n\t"
        "W%=:\n\t"
        "mbarrier.try_wait.parity.acquire.cta.shared::cta.b64 P, [%0], %1, 0x989680;\n\t"
        "@P bra.uni D%=;\n\t"
        "bra.uni W%=;\n\t"
        "D%=:\n\t}"
        :: "r"(mbar), "r"(phase) : "memory");
}

extern __shared__ char smem[];

__global__ void __launch_bounds__(NT, 3)
topk_kernel(const float* __restrict__ x, float* __restrict__ out)
{
    u64*      slist = (u64*)(smem + OFF_SLIST);
    unsigned* hist  = (unsigned*)(smem + OFF_HIST);
    unsigned* S     = (unsigned*)(smem + OFF_S);   // 2:m 3:jbin 4:nab 5:cnt_in 6:total
    const unsigned mb0 = smem_u32(smem + OFF_MBAR);
    float4* s4 = (float4*)smem;
    float*  sf = (float*)smem;

    const int tid = threadIdx.x, lane = tid & 31, wid = tid >> 5;
    const size_t row = blockIdx.x;
    const float* __restrict__ xrow = x + row * COLS;
    float* __restrict__ orow = out + row * COLS;
    float4* __restrict__ orow4 = (float4*)orow;

    // ---- tid0: init mbarriers + issue ALL 4 chunked TMA loads upfront ----
    if (tid == 0) {
        S[2] = 0;
        #pragma unroll
        for (int ch = 0; ch < NCH; ch++)
            asm volatile("mbarrier.init.shared.b64 [%0], 1;" :: "r"(mb0 + ch * 8) : "memory");
        asm volatile("fence.proxy.async.shared::cta;" ::: "memory");
        #pragma unroll
        for (int ch = 0; ch < NCH; ch++) {
            asm volatile("mbarrier.arrive.expect_tx.shared.b64 _, [%0], %1;"
                         :: "r"(mb0 + ch * 8), "n"(CHBYTES) : "memory");
            asm volatile("cp.async.bulk.shared::cluster.global.mbarrier::complete_tx::bytes [%0], [%1], %2, [%3];"
                         :: "r"(smem_u32(smem) + ch * CHBYTES), "l"(xrow + ch * CHELEM),
                            "n"(CHBYTES), "r"(mb0 + ch * 8) : "memory");
        }
    }
    if (tid < 256) hist[tid] = 0;
    __syncthreads();

    // ---- pass 1: per-chunk wait + histogram + EARLY zero-stores ----
    // A float4 with no element >= 1.9 is final output zero4 -> STG it now,
    // overlapping the remaining TMA loads (both DRAM directions stream at once).
    const unsigned winB0 = 0x3FF33333u;     // bits(1.9f): ~470 expected for N(0,1)
    const unsigned span0 = 0x7F800001u - winB0;
    const float4 z4 = make_float4(0.f, 0.f, 0.f, 0.f);
    unsigned cmask = 0;                      // bit per owned element that is >= 1.9
    #pragma unroll
    for (int ch = 0; ch < NCH; ch++) {
        mbar_wait(mb0 + ch * 8, 0);
        #pragma unroll
        for (int c = 0; c < 2; c++) {
            const int pos = ch * CHF4 + c * NT + tid;
            float4 t = s4[pos];
            unsigned bb[4] = { __float_as_uint(t.x) - winB0, __float_as_uint(t.y) - winB0,
                               __float_as_uint(t.z) - winB0, __float_as_uint(t.w) - winB0 };
            unsigned nib = 0;
            #pragma unroll
            for (int e = 0; e < 4; e++) {
                if (bb[e] < span0) {
                    atomicAdd(&hist[min(bb[e] >> 17, 255u)], 1u);
                    nib |= 1u << e;
                }
            }
            if (nib == 0) orow4[pos] = z4;                   // final: pure zero slot
            else cmask |= nib << (ch * 8 + c * 4);           // defer candidate slot
        }
    }
    __syncthreads();

    // ---- narrowing loop (round 0 reuses pass-1 hist) ----
    unsigned winB = winB0, span = span0;
    int sh = 17;
    unsigned need = KSEL;
    unsigned bLo = 0x7F800001u, bThr = 0x7F800001u;  // sentinel: selects nothing
    bool fellback = false, maskvalid = true;

    for (int r = 0; r < 10; r++) {
        if (r > 0) {   // re-histogram full row from smem (rare paths)
            #pragma unroll 1
            for (int i = 0; i < 8; i++) {
                float4 t = s4[tid + i * NT];
                unsigned b0 = __float_as_uint(t.x) - winB, b1 = __float_as_uint(t.y) - winB;
                unsigned b2 = __float_as_uint(t.z) - winB, b3 = __float_as_uint(t.w) - winB;
                if (b0 < span) atomicAdd(&hist[min(b0 >> sh, 255u)], 1u);
                if (b1 < span) atomicAdd(&hist[min(b1 >> sh, 255u)], 1u);
                if (b2 < span) atomicAdd(&hist[min(b2 >> sh, 255u)], 1u);
                if (b3 < span) atomicAdd(&hist[min(b3 >> sh, 255u)], 1u);
            }
            __syncthreads();
        }
        // warp0: suffix sums over 256 bins + boundary find
        if (wid == 0) {
            uint4 a = *(uint4*)&hist[8 * lane];
            uint4 b = *(uint4*)&hist[8 * lane + 4];
            unsigned s7 = b.w, s6 = b.z + s7, s5 = b.y + s6, s4v = b.x + s5;
            unsigned s3 = a.w + s4v, s2 = a.z + s3, s1 = a.y + s2, s0 = a.x + s1;
            unsigned suf = s0;
            #pragma unroll
            for (int d = 1; d < 32; d <<= 1) {
                unsigned n = __shfl_down_sync(0xFFFFFFFFu, suf, d);
                if (lane + d < 32) suf += n;
            }
            if (lane == 0) S[6] = suf;
            unsigned add = suf - s0;
            unsigned sv[8] = { s0, s1, s2, s3, s4v, s5, s6, s7 };
            #pragma unroll
            for (int i = 0; i < 8; i++) {
                unsigned Sv = sv[i] + add;
                unsigned Sn = (i < 7) ? (sv[i + 1] + add) : add;
                if (Sv >= need && Sn < need) { S[3] = 8u*lane + i; S[4] = Sn; S[5] = Sv - Sn; }
            }
        }
        __syncthreads();

        unsigned C = S[6];
        if (C < need && !fellback) {
            // <256 above 1.9: re-histogram over ALL positives (exact: non-positive
            // top-K entries ReLU to 0 == background, invisible)
            fellback = true; maskvalid = false;
            winB = 1u; span = 0x7F800000u; sh = 23;
            if (tid < 256) hist[tid] = 0;
            __syncthreads();
            continue;
        }
        if (C <= need) { bLo = winB; bThr = winB; break; }  // every candidate wins

        unsigned jbin = S[3], nab = S[4], cnt_in = S[5];
        bool clamped = ((span - 1u) >> sh) > 255u;
        unsigned newLo = winB + (jbin << sh);
        unsigned newSpan = (clamped && jbin == 255u) ? (span - (255u << sh)) : (1u << sh);
        need -= nab;
        if (cnt_in <= 32u || sh == 0) { bLo = newLo; bThr = newLo + newSpan; break; }
        winB = newLo; span = newSpan;
        int t = 32 - __clz(newSpan - 1u) - 8;
        sh = (t < 0) ? 0 : t;
        if (tid < 256) hist[tid] = 0;
        __syncthreads();
    }

    // ---- combined walk: candidate-slot select-store + boundary-window gather ----
    const unsigned thrSpan = 0x80000000u - bThr;  // positive & >= bThr
    const unsigned winSpan = bThr - bLo;
    if (maskvalid) {
        unsigned mm = cmask;
        while (mm) {
            int b = __ffs(mm) - 1;
            int slot = b >> 2;                       // which of 8 float4 slots
            mm &= ~(0xFu << (slot * 4));             // consume whole nibble
            const int pos = (slot >> 1) * CHF4 + (slot & 1) * NT + tid;
            float4 t = s4[pos];
            float f[4] = { t.x, t.y, t.z, t.w };
            float vv[4];
            unsigned idx0 = 4u * (unsigned)pos;
            #pragma unroll
            for (int e = 0; e < 4; e++) {
                unsigned bits = __float_as_uint(f[e]);
                vv[e] = ((bits - bThr) < thrSpan) ? f[e] : 0.0f;
                if ((bits - bLo) < winSpan) {        // rare boundary element
                    unsigned p = atomicAdd(&S[2], 1u);
                    if (p < WCAP) slist[p] = ((u64)bits << 32) | (unsigned)~(idx0 + e);
                }
            }
            orow4[pos] = make_float4(vv[0], vv[1], vv[2], vv[3]);
        }
    } else {
        // fallback: full-row select-rewrite (same thread->address mapping as the
        // early zero-stores, so program order makes this store win)
        #pragma unroll 1
        for (int i = 0; i < 8; i++) {
            float4 t = s4[tid + i * NT];
            float f[4] = { t.x, t.y, t.z, t.w };
            float vv[4];
            unsigned idx0 = 4u * (unsigned)(tid + i * NT);
            #pragma unroll
            for (int e = 0; e < 4; e++) {
                unsigned bits = __float_as_uint(f[e]);
                vv[e] = ((bits - bThr) < thrSpan) ? f[e] : 0.0f;
                if ((bits - bLo) < winSpan) {
                    unsigned p = atomicAdd(&S[2], 1u);
                    if (p < WCAP) slist[p] = ((u64)bits << 32) | (unsigned)~(idx0 + e);
                }
            }
            orow4[tid + i * NT] = make_float4(vv[0], vv[1], vv[2], vv[3]);
        }
    }
    __syncthreads();   // slist complete; conflicting STG.128s ordered before winners

    // ---- exact stable rank on tiny boundary window; scatter ranked winners ----
    unsigned m = S[2]; if (m > WCAP) m = WCAP;
    if ((unsigned)tid < m) {
        u64 mine = slist[tid];
        unsigned rk = 0;
        for (unsigned q = 0; q < m; q++) rk += (slist[q] > mine);
        if (rk < need)     // key desc, index asc (low word is ~idx)
            orow[~(unsigned)mine] = __uint_as_float((unsigned)(mine >> 32));
    }
}

extern "C" void kernel_launch(void* const* d_in, const int* in_sizes, int n_in,
                              void* d_out, int out_size) {
    const float* x = (const float*)d_in[0];
    float* out = (float*)d_out;
    int rows = in_sizes[0] / COLS;
    cudaFuncSetAttribute(topk_kernel, cudaFuncAttributeMaxDynamicSharedMemorySize, SMEM_TOTAL);
    topk_kernel<<<rows, NT, SMEM_TOTAL>>>(x, out);
}

// round 15
// speedup vs baseline: 1.0655x; 1.0655x over previous
#include <cuda_runtime.h>
#include <cstdint>

#define COLS 16384
#define KSEL 256
#define NT   512
#define WCAP 512
#define ROWBYTES (COLS * 4)
#define NCH  4
#define CHBYTES (ROWBYTES / NCH)   // 16384
#define CHF4    (CHBYTES / 16)     // 1024 float4 per chunk
#define CHELEM  (CHBYTES / 4)      // 4096 floats per chunk

// dynamic smem layout
#define OFF_SLIST 65536
#define OFF_HIST  (OFF_SLIST + WCAP * 8)   // 69632
#define OFF_S     (OFF_HIST + 1024)        // 70656
#define OFF_MBAR  (OFF_S + 32)             // 70688
#define SMEM_TOTAL (OFF_MBAR + NCH * 8)    // 70720 -> 3 CTAs/SM

typedef unsigned long long u64;

__device__ __forceinline__ unsigned smem_u32(const void* p) {
    unsigned r;
    asm("{ .reg .u64 t; cvta.to.shared.u64 t, %1; cvt.u32.u64 %0, t; }" : "=r"(r) : "l"(p));
    return r;
}
__device__ __forceinline__ void mbar_wait(unsigned mbar, unsigned phase) {
    asm volatile(
        "{\n\t.reg .pred P;\n\t"
        "W%=:\n\t"
        "mbarrier.try_wait.parity.acquire.cta.shared::cta.b64 P, [%0], %1, 0x989680;\n\t"
        "@P bra.uni D%=;\n\t"
        "bra.uni W%=;\n\t"
        "D%=:\n\t}"
        :: "r"(mbar), "r"(phase) : "memory");
}

extern __shared__ char smem[];

__global__ void __launch_bounds__(NT, 3)
topk_kernel(const float* __restrict__ x, float* __restrict__ out)
{
    u64*      slist = (u64*)(smem + OFF_SLIST);
    unsigned* hist  = (unsigned*)(smem + OFF_HIST);
    unsigned* S     = (unsigned*)(smem + OFF_S);   // 2:m 3:jbin 4:nab 5:cnt_in 6:total
    const unsigned mb0 = smem_u32(smem + OFF_MBAR);
    float4* s4 = (float4*)smem;

    const int tid = threadIdx.x, lane = tid & 31, wid = tid >> 5;
    const size_t row = blockIdx.x;
    const float* __restrict__ xrow = x + row * COLS;
    float* __restrict__ orow = out + row * COLS;
    float4* __restrict__ orow4 = (float4*)orow;

    // ---- tid0: init mbarriers + issue ALL 4 chunked TMA loads upfront ----
    if (tid == 0) {
        S[2] = 0;
        #pragma unroll
        for (int ch = 0; ch < NCH; ch++)
            asm volatile("mbarrier.init.shared.b64 [%0], 1;" :: "r"(mb0 + ch * 8) : "memory");
        asm volatile("fence.proxy.async.shared::cta;" ::: "memory");
        #pragma unroll
        for (int ch = 0; ch < NCH; ch++) {
            asm volatile("mbarrier.arrive.expect_tx.shared.b64 _, [%0], %1;"
                         :: "r"(mb0 + ch * 8), "n"(CHBYTES) : "memory");
            asm volatile("cp.async.bulk.shared::cluster.global.mbarrier::complete_tx::bytes [%0], [%1], %2, [%3];"
                         :: "r"(smem_u32(smem) + ch * CHBYTES), "l"(xrow + ch * CHELEM),
                            "n"(CHBYTES), "r"(mb0 + ch * 8) : "memory");
        }
    }
    if (tid < 256) hist[tid] = 0;
    __syncthreads();

    // ---- pass 1: per-chunk wait + histogram only (R12 verbatim; no stores) ----
    const unsigned winB0 = 0x3FF33333u;     // bits(1.9f): ~470 expected for N(0,1)
    const unsigned span0 = 0x7F800001u - winB0;
    unsigned cmask = 0;                      // bit per owned element that is >= 1.9
    #pragma unroll
    for (int ch = 0; ch < NCH; ch++) {
        mbar_wait(mb0 + ch * 8, 0);
        #pragma unroll
        for (int c = 0; c < 2; c++) {
            float4 t = s4[ch * CHF4 + c * NT + tid];
            unsigned bb[4] = { __float_as_uint(t.x) - winB0, __float_as_uint(t.y) - winB0,
                               __float_as_uint(t.z) - winB0, __float_as_uint(t.w) - winB0 };
            #pragma unroll
            for (int e = 0; e < 4; e++) {
                if (bb[e] < span0) {
                    atomicAdd(&hist[min(bb[e] >> 17, 255u)], 1u);
                    cmask |= 1u << (ch * 8 + c * 4 + e);
                }
            }
        }
    }
    __syncthreads();

    // ---- narrowing loop (round 0 reuses pass-1 hist) ----
    unsigned winB = winB0, span = span0;
    int sh = 17;
    unsigned need = KSEL;
    unsigned bLo = 0x7F800001u, bThr = 0x7F800001u;  // sentinel: selects nothing
    bool fellback = false, maskvalid = true;

    for (int r = 0; r < 10; r++) {
        if (r > 0) {   // re-histogram full row from smem (rare paths)
            #pragma unroll 1
            for (int i = 0; i < 8; i++) {
                float4 t = s4[tid + i * NT];
                unsigned b0 = __float_as_uint(t.x) - winB, b1 = __float_as_uint(t.y) - winB;
                unsigned b2 = __float_as_uint(t.z) - winB, b3 = __float_as_uint(t.w) - winB;
                if (b0 < span) atomicAdd(&hist[min(b0 >> sh, 255u)], 1u);
                if (b1 < span) atomicAdd(&hist[min(b1 >> sh, 255u)], 1u);
                if (b2 < span) atomicAdd(&hist[min(b2 >> sh, 255u)], 1u);
                if (b3 < span) atomicAdd(&hist[min(b3 >> sh, 255u)], 1u);
            }
            __syncthreads();
        }
        // warp0: suffix sums over 256 bins + boundary find
        if (wid == 0) {
            uint4 a = *(uint4*)&hist[8 * lane];
            uint4 b = *(uint4*)&hist[8 * lane + 4];
            unsigned s7 = b.w, s6 = b.z + s7, s5 = b.y + s6, s4v = b.x + s5;
            unsigned s3 = a.w + s4v, s2 = a.z + s3, s1 = a.y + s2, s0 = a.x + s1;
            unsigned suf = s0;
            #pragma unroll
            for (int d = 1; d < 32; d <<= 1) {
                unsigned n = __shfl_down_sync(0xFFFFFFFFu, suf, d);
                if (lane + d < 32) suf += n;
            }
            if (lane == 0) S[6] = suf;
            unsigned add = suf - s0;
            unsigned sv[8] = { s0, s1, s2, s3, s4v, s5, s6, s7 };
            #pragma unroll
            for (int i = 0; i < 8; i++) {
                unsigned Sv = sv[i] + add;
                unsigned Sn = (i < 7) ? (sv[i + 1] + add) : add;
                if (Sv >= need && Sn < need) { S[3] = 8u*lane + i; S[4] = Sn; S[5] = Sv - Sn; }
            }
        }
        __syncthreads();

        unsigned C = S[6];
        if (C < need && !fellback) {
            // <256 above 1.9: re-histogram over ALL positives (exact: non-positive
            // top-K entries ReLU to 0 == background, invisible)
            fellback = true; maskvalid = false;
            winB = 1u; span = 0x7F800000u; sh = 23;
            if (tid < 256) hist[tid] = 0;
            __syncthreads();
            continue;
        }
        if (C <= need) { bLo = winB; bThr = winB; break; }  // every candidate wins

        unsigned jbin = S[3], nab = S[4], cnt_in = S[5];
        bool clamped = ((span - 1u) >> sh) > 255u;
        unsigned newLo = winB + (jbin << sh);
        unsigned newSpan = (clamped && jbin == 255u) ? (span - (255u << sh)) : (1u << sh);
        need -= nab;
        if (cnt_in <= 32u || sh == 0) { bLo = newLo; bThr = newLo + newSpan; break; }
        winB = newLo; span = newSpan;
        int t = 32 - __clz(newSpan - 1u) - 8;
        sh = (t < 0) ? 0 : t;
        if (tid < 256) hist[tid] = 0;
        __syncthreads();
    }

    // ---- pass 2: direct STG output; zero slots need NO smem read ----
    const unsigned thrSpan = 0x80000000u - bThr;  // positive & >= bThr
    const unsigned winSpan = bThr - bLo;
    const float4 z4 = make_float4(0.f, 0.f, 0.f, 0.f);
    if (maskvalid) {
        #pragma unroll
        for (int ch = 0; ch < NCH; ch++) {
            #pragma unroll
            for (int c = 0; c < 2; c++) {
                const int pos = ch * CHF4 + c * NT + tid;
                unsigned nib = (cmask >> (ch * 8 + c * 4)) & 0xFu;
                if (nib == 0) {
                    orow4[pos] = z4;                 // 97% of slots: pure zero, no read
                } else {
                    float4 t = s4[pos];
                    float f[4] = { t.x, t.y, t.z, t.w };
                    float vv[4];
                    unsigned idx0 = 4u * (unsigned)pos;
                    #pragma unroll
                    for (int e = 0; e < 4; e++) {
                        unsigned bits = __float_as_uint(f[e]);
                        vv[e] = ((bits - bThr) < thrSpan) ? f[e] : 0.0f;
                        if ((bits - bLo) < winSpan) {    // rare boundary element
                            unsigned p = atomicAdd(&S[2], 1u);
                            if (p < WCAP) slist[p] = ((u64)bits << 32) | (unsigned)~(idx0 + e);
                        }
                    }
                    orow4[pos] = make_float4(vv[0], vv[1], vv[2], vv[3]);
                }
            }
        }
    } else {
        // fallback: full select-rewrite from smem
        #pragma unroll 1
        for (int i = 0; i < 8; i++) {
            float4 t = s4[tid + i * NT];
            float f[4] = { t.x, t.y, t.z, t.w };
            float vv[4];
            unsigned idx0 = 4u * (unsigned)(tid + i * NT);
            #pragma unroll
            for (int e = 0; e < 4; e++) {
                unsigned bits = __float_as_uint(f[e]);
                vv[e] = ((bits - bThr) < thrSpan) ? f[e] : 0.0f;
                if ((bits - bLo) < winSpan) {
                    unsigned p = atomicAdd(&S[2], 1u);
                    if (p < WCAP) slist[p] = ((u64)bits << 32) | (unsigned)~(idx0 + e);
                }
            }
            orow4[tid + i * NT] = make_float4(vv[0], vv[1], vv[2], vv[3]);
        }
    }
    __syncthreads();   // slist complete; pre-sync STG.128s ordered before winner STGs

    // ---- exact stable rank on tiny boundary window; scatter ranked winners ----
    unsigned m = S[2]; if (m > WCAP) m = WCAP;
    if ((unsigned)tid < m) {
        u64 mine = slist[tid];
        unsigned rk = 0;
        for (unsigned q = 0; q < m; q++) rk += (slist[q] > mine);
        if (rk < need)     // key desc, index asc (low word is ~idx)
            orow[~(unsigned)mine] = __uint_as_float((unsigned)(mine >> 32));
    }
}

extern "C" void kernel_launch(void* const* d_in, const int* in_sizes, int n_in,
                              void* d_out, int out_size) {
    const float* x = (const float*)d_in[0];
    float* out = (float*)d_out;
    int rows = in_sizes[0] / COLS;
    cudaFuncSetAttribute(topk_kernel, cudaFuncAttributeMaxDynamicSharedMemorySize, SMEM_TOTAL);
    topk_kernel<<<rows, NT, SMEM_TOTAL>>>(x, out);
}